// round 5
// baseline (speedup 1.0000x reference)
#include <cuda_runtime.h>
#include <cuda_fp16.h>
#include <mma.h>
#include <stdint.h>

using namespace nvcuda;

#define N_MAX 100000
#define E_MAX 3200000

// ---------------- scratch (static device globals; no allocation) ----------------
__device__ int   g_deg[N_MAX];
__device__ int   g_rowptr[N_MAX + 1];
__device__ int   g_cursor[N_MAX];
__device__ unsigned int g_blkpub[128];   // lookback: bit31=inclusive, bit30=aggregate
__device__ int2  g_cw[E_MAX];            // (src index, weight bits fp32)
__device__ float g_dinv[N_MAX];
__device__ __align__(16) __half g_x16[N_MAX * 32];    // padded input fp16
__device__ __align__(16) __half g_abuf[N_MAX * 64];   // agg outputs / GEMM A; also t
__device__ __align__(16) __half g_hbuf[N_MAX * 128];  // h1, h2
__device__ __align__(16) __half g_w1h[32 * 64];       // W1 padded 21->32 rows
__device__ __align__(16) __half g_w2h[64 * 128];
__device__ __align__(16) __half g_w3h[128 * 64];
__device__ int   g_is64;

// ---------------- pre: sniff, pad x, zero deg + lookback flags, weights --------
__global__ void k_pre(const float* __restrict__ x, const unsigned int* __restrict__ ew,
                      const float* __restrict__ W1, const float* __restrict__ W2,
                      const float* __restrict__ W3, int n) {
    if (blockIdx.x == 0) {
        if (threadIdx.x == 0) g_is64 = 1;
        __syncthreads();
        bool hit = false;
        #pragma unroll 4
        for (int s = 0; s < 32; s++) {
            int i = threadIdx.x * 32 + s;
            if (ew[2 * i + 1] != 0u) hit = true;
        }
        if (hit) g_is64 = 0;
    }
    int idx = blockIdx.x * blockDim.x + threadIdx.x;
    if (idx < n * 32) {
        int i = idx >> 5, f = idx & 31;
        g_x16[idx] = __float2half((f < 21) ? x[i * 21 + f] : 0.f);
    }
    if (idx < n) g_deg[idx] = 0;
    if (idx < 128) g_blkpub[idx] = 0u;
    if (idx < 2048) {                 // W1 pad to 32x64
        int r = idx >> 6, c = idx & 63;
        g_w1h[idx] = __float2half((r < 21) ? W1[r * 64 + c] : 0.f);
    }
    if (idx < 8192) g_w2h[idx] = __float2half(W2[idx]);
    if (idx < 8192) g_w3h[idx] = __float2half(W3[idx]);
}

// ---------------- degree histogram: 4 edges per thread ----------------
__global__ void k_deg(const int* __restrict__ ei32, int E) {
    int e = (blockIdx.x * blockDim.x + threadIdx.x) << 2;
    if (e >= E) return;
    int is64 = g_is64;
    int m = E - e; if (m > 4) m = 4;
    if (((E & 3) == 0) && m == 4) {
        int d[4];
        if (is64) {
            const int4* p = (const int4*)((const long long*)ei32 + E + e);
            int4 q0 = p[0], q1 = p[1];
            d[0] = q0.x; d[1] = q0.z; d[2] = q1.x; d[3] = q1.z;
        } else {
            int4 q = *(const int4*)(ei32 + E + e);
            d[0] = q.x; d[1] = q.y; d[2] = q.z; d[3] = q.w;
        }
        atomicAdd(&g_deg[d[0]], 1); atomicAdd(&g_deg[d[1]], 1);
        atomicAdd(&g_deg[d[2]], 1); atomicAdd(&g_deg[d[3]], 1);
    } else {
        for (int j = 0; j < m; j++) {
            int dd = is64 ? ei32[(E + e + j) << 1] : ei32[E + e + j];
            atomicAdd(&g_deg[dd], 1);
        }
    }
}

// ---------------- single-pass scan: block scan + decoupled lookback ------------
// grid <= 148 blocks (all resident), 1024 threads. Writes rowptr, cursor, dinv.
__global__ void k_scan(int n, int E) {
    __shared__ int wsum[32];
    __shared__ int s_prefix;
    int tid = threadIdx.x, bid = blockIdx.x;
    int i = bid * 1024 + tid;
    int v = (i < n) ? g_deg[i] : 0;
    if (i < n) g_dinv[i] = rsqrtf((float)(v + 1));   // self-loop included
    int lane = tid & 31, wid = tid >> 5;
    int inc = v;
    #pragma unroll
    for (int off = 1; off < 32; off <<= 1) {
        int t = __shfl_up_sync(0xffffffffu, inc, off);
        if (lane >= off) inc += t;
    }
    if (lane == 31) wsum[wid] = inc;
    __syncthreads();
    if (wid == 0) {
        int s = wsum[lane];
        #pragma unroll
        for (int off = 1; off < 32; off <<= 1) {
            int t = __shfl_up_sync(0xffffffffu, s, off);
            if (lane >= off) s += t;
        }
        wsum[lane] = s;
    }
    __syncthreads();
    int total = wsum[31];
    if (tid == 0) {
        if (bid == 0) {
            atomicExch(&g_blkpub[0], 0x80000000u | (unsigned)total);
            s_prefix = 0;
        } else {
            atomicExch(&g_blkpub[bid], 0x40000000u | (unsigned)total);
            int prefix = 0;
            for (int p = bid - 1; p >= 0; p--) {
                unsigned s;
                do { s = atomicAdd(&g_blkpub[p], 0u); } while (!(s & 0xC0000000u));
                prefix += (int)(s & 0x3FFFFFFFu);
                if (s & 0x80000000u) break;
            }
            atomicExch(&g_blkpub[bid], 0x80000000u | (unsigned)(prefix + total));
            s_prefix = prefix;
        }
        if (bid == 0) g_rowptr[n] = E;
    }
    __syncthreads();
    int base = (wid > 0) ? wsum[wid - 1] : 0;
    if (i < n) {
        int r = s_prefix + base + inc - v;   // exclusive
        g_rowptr[i] = r;
        g_cursor[i] = r;
    }
}

// ---------------- CSR scatter: 4 edges per thread, vectorized loads ------------
__global__ void k_scatter(const int* __restrict__ ei32, int E) {
    int e = (blockIdx.x * blockDim.x + threadIdx.x) << 2;
    if (e >= E) return;
    int is64 = g_is64;
    int m = E - e; if (m > 4) m = 4;
    if (((E & 3) == 0) && m == 4) {
        int s[4], d[4];
        if (is64) {
            const int4* ps = (const int4*)((const long long*)ei32 + e);
            int4 a0 = ps[0], a1 = ps[1];
            s[0] = a0.x; s[1] = a0.z; s[2] = a1.x; s[3] = a1.z;
            const int4* pd = (const int4*)((const long long*)ei32 + E + e);
            int4 b0 = pd[0], b1 = pd[1];
            d[0] = b0.x; d[1] = b0.z; d[2] = b1.x; d[3] = b1.z;
        } else {
            int4 a = *(const int4*)(ei32 + e);
            s[0] = a.x; s[1] = a.y; s[2] = a.z; s[3] = a.w;
            int4 b = *(const int4*)(ei32 + E + e);
            d[0] = b.x; d[1] = b.y; d[2] = b.z; d[3] = b.w;
        }
        #pragma unroll
        for (int j = 0; j < 4; j++) {
            int pos = atomicAdd(&g_cursor[d[j]], 1);
            float w = g_dinv[s[j]] * g_dinv[d[j]];
            g_cw[pos] = make_int2(s[j], __float_as_int(w));
        }
    } else {
        for (int j = 0; j < m; j++) {
            int src = is64 ? ei32[(e + j) << 1] : ei32[e + j];
            int dst = is64 ? ei32[(E + e + j) << 1] : ei32[E + e + j];
            int pos = atomicAdd(&g_cursor[dst], 1);
            float w = g_dinv[src] * g_dinv[dst];
            g_cw[pos] = make_int2(src, __float_as_int(w));
        }
    }
}

// ---------------- aggregation: warp/node, double-buffered edge staging ----------
// 32 halfs per row
__global__ void k_agg_h32(const __half* __restrict__ h, __half* __restrict__ out, int n) {
    __shared__ int2 scw[8][2][32];
    int w = threadIdx.x >> 5, lane = threadIdx.x & 31;
    int gw = blockIdx.x * 8 + w;
    if (gw >= n) return;
    int start = g_rowptr[gw], end = g_rowptr[gw + 1];
    float di = g_dinv[gw];
    float acc = di * di * __half2float(h[(gw << 5) + lane]);
    int nchunks = (end - start + 31) >> 5;
    if (start + lane < end) scw[w][0][lane] = g_cw[start + lane];
    __syncwarp();
    int buf = 0;
    for (int c = 0; c < nchunks; c++) {
        int k = start + (c << 5);
        if (c + 1 < nchunks && k + 32 + lane < end)
            scw[w][buf ^ 1][lane] = g_cw[k + 32 + lane];
        int cnt = end - k; if (cnt > 32) cnt = 32;
        int j = 0;
        for (; j + 8 <= cnt; j += 8) {
            int2 cc[8];
            #pragma unroll
            for (int u = 0; u < 8; u++) cc[u] = scw[w][buf][j + u];
            float v[8];
            #pragma unroll
            for (int u = 0; u < 8; u++) v[u] = __half2float(h[(cc[u].x << 5) + lane]);
            #pragma unroll
            for (int u = 0; u < 8; u++) acc += __int_as_float(cc[u].y) * v[u];
        }
        for (; j < cnt; j++) {
            int2 cc = scw[w][buf][j];
            acc += __int_as_float(cc.y) * __half2float(h[(cc.x << 5) + lane]);
        }
        __syncwarp();
        buf ^= 1;
    }
    out[(gw << 5) + lane] = __float2half_rn(acc);
}

// 64 halfs per row = 32 half2 per row
__global__ void k_agg_h64(const __half2* __restrict__ h2, __half2* __restrict__ o2, int n) {
    __shared__ int2 scw[8][2][32];
    int w = threadIdx.x >> 5, lane = threadIdx.x & 31;
    int gw = blockIdx.x * 8 + w;
    if (gw >= n) return;
    int start = g_rowptr[gw], end = g_rowptr[gw + 1];
    float di = g_dinv[gw];
    float sw = di * di;
    float2 hv = __half22float2(h2[(gw << 5) + lane]);
    float ax = sw * hv.x, ay = sw * hv.y;
    int nchunks = (end - start + 31) >> 5;
    if (start + lane < end) scw[w][0][lane] = g_cw[start + lane];
    __syncwarp();
    int buf = 0;
    for (int c = 0; c < nchunks; c++) {
        int k = start + (c << 5);
        if (c + 1 < nchunks && k + 32 + lane < end)
            scw[w][buf ^ 1][lane] = g_cw[k + 32 + lane];
        int cnt = end - k; if (cnt > 32) cnt = 32;
        int j = 0;
        for (; j + 8 <= cnt; j += 8) {
            int2 cc[8];
            #pragma unroll
            for (int u = 0; u < 8; u++) cc[u] = scw[w][buf][j + u];
            float2 v[8];
            #pragma unroll
            for (int u = 0; u < 8; u++) v[u] = __half22float2(h2[(cc[u].x << 5) + lane]);
            #pragma unroll
            for (int u = 0; u < 8; u++) {
                float wt = __int_as_float(cc[u].y);
                ax += wt * v[u].x; ay += wt * v[u].y;
            }
        }
        for (; j < cnt; j++) {
            int2 cc = scw[w][buf][j];
            float2 v = __half22float2(h2[(cc.x << 5) + lane]);
            float wt = __int_as_float(cc.y);
            ax += wt * v.x; ay += wt * v.y;
        }
        __syncwarp();
        buf ^= 1;
    }
    o2[(gw << 5) + lane] = __floats2half2_rn(ax, ay);
}

// ---------------- HMMA GEMM: A[n,K]fp16 @ W[K,N]fp16 (+bias, relu) -> fp16 ------
template<int K, int N, int RELU, int BIAS>
__global__ void k_hgemm(const __half* __restrict__ A, const __half* __restrict__ Wh,
                        const float* __restrict__ bias, __half* __restrict__ C, int n) {
    constexpr int CF = N / 64;
    constexpr int SZ_AB = (64 * K + K * N) * 2;
    constexpr int SZ_C = 64 * N * 4;
    constexpr int SZ = SZ_AB > SZ_C ? SZ_AB : SZ_C;
    __shared__ __align__(16) char smem[SZ];
    __half* sA = (__half*)smem;
    __half* sB = (__half*)(smem + 64 * K * 2);
    float*  sC = (float*)smem;

    int tid = threadIdx.x;
    int rowBase = blockIdx.x * 64;

    constexpr int AV = 64 * K / 8;
    for (int v = tid; v < AV; v += 256) {
        int r = v / (K / 8);
        int c8 = (v % (K / 8)) * 8;
        int4 val = make_int4(0, 0, 0, 0);
        int row = rowBase + r;
        if (row < n) val = *(const int4*)(A + (size_t)row * K + c8);
        *(int4*)(sA + r * K + c8) = val;
    }
    constexpr int BV = K * N / 8;
    for (int v = tid; v < BV; v += 256)
        *(int4*)(sB + v * 8) = *(const int4*)(Wh + v * 8);
    __syncthreads();

    int wid = tid >> 5;
    int wr = wid >> 2, wc = wid & 3;
    wmma::fragment<wmma::accumulator, 16, 16, 16, float> acc[2][CF];
    #pragma unroll
    for (int i = 0; i < 2; i++)
        #pragma unroll
        for (int j = 0; j < CF; j++)
            wmma::fill_fragment(acc[i][j], 0.f);

    #pragma unroll
    for (int k = 0; k < K; k += 16) {
        wmma::fragment<wmma::matrix_a, 16, 16, 16, __half, wmma::row_major> af[2];
        wmma::fragment<wmma::matrix_b, 16, 16, 16, __half, wmma::row_major> bf[CF];
        #pragma unroll
        for (int i = 0; i < 2; i++)
            wmma::load_matrix_sync(af[i], sA + (wr * 32 + i * 16) * K + k, K);
        #pragma unroll
        for (int j = 0; j < CF; j++)
            wmma::load_matrix_sync(bf[j], sB + k * N + (wc * CF + j) * 16, N);
        #pragma unroll
        for (int i = 0; i < 2; i++)
            #pragma unroll
            for (int j = 0; j < CF; j++)
                wmma::mma_sync(acc[i][j], af[i], bf[j], acc[i][j]);
    }
    __syncthreads();
    #pragma unroll
    for (int i = 0; i < 2; i++)
        #pragma unroll
        for (int j = 0; j < CF; j++)
            wmma::store_matrix_sync(sC + (wr * 32 + i * 16) * N + (wc * CF + j) * 16,
                                    acc[i][j], N, wmma::mem_row_major);
    __syncthreads();

    constexpr int EV = 64 * N / 4;
    for (int v = tid; v < EV; v += 256) {
        int r = v / (N / 4);
        int c4 = (v % (N / 4)) * 4;
        int row = rowBase + r;
        if (row >= n) continue;
        float4 p = *(const float4*)(sC + r * N + c4);
        float v0 = p.x, v1 = p.y, v2 = p.z, v3 = p.w;
        if (BIAS) {
            v0 += bias[c4]; v1 += bias[c4 + 1]; v2 += bias[c4 + 2]; v3 += bias[c4 + 3];
        }
        if (RELU) {
            v0 = fmaxf(v0, 0.f); v1 = fmaxf(v1, 0.f);
            v2 = fmaxf(v2, 0.f); v3 = fmaxf(v3, 0.f);
        }
        __half2 h0 = __floats2half2_rn(v0, v1);
        __half2 h1 = __floats2half2_rn(v2, v3);
        *(int2*)(C + (size_t)row * N + c4) = make_int2(*(int*)&h0, *(int*)&h1);
    }
}

// ---------------- fused: a3 = Â t  then  head MLP, one kernel -------------------
__global__ void k_agg_head(const __half2* __restrict__ h2, const float* __restrict__ b3,
                           const float* __restrict__ Wl1, const float* __restrict__ bl1,
                           const float* __restrict__ Wl2, const float* __restrict__ bl2,
                           float* __restrict__ out, int n) {
    __shared__ int2 scw[8][2][32];
    __shared__ float sW1[64 * 20];
    __shared__ float sT[8][64];
    __shared__ float sb3[64], sb1[20], sW2[20];
    __shared__ float sb2;
    int tid = threadIdx.x;
    for (int i = tid; i < 1280; i += 256) sW1[i] = Wl1[i];
    if (tid < 64) sb3[tid] = b3[tid];
    if (tid < 20) { sb1[tid] = bl1[tid]; sW2[tid] = Wl2[tid]; }
    if (tid == 0) sb2 = bl2[0];
    __syncthreads();

    int w = tid >> 5, lane = tid & 31;
    int gw = blockIdx.x * 8 + w;
    if (gw >= n) return;
    int start = g_rowptr[gw], end = g_rowptr[gw + 1];
    float di = g_dinv[gw];
    float sw = di * di;
    float2 hv = __half22float2(h2[(gw << 5) + lane]);
    float ax = sw * hv.x, ay = sw * hv.y;
    int nchunks = (end - start + 31) >> 5;
    if (start + lane < end) scw[w][0][lane] = g_cw[start + lane];
    __syncwarp();
    int buf = 0;
    for (int c = 0; c < nchunks; c++) {
        int k = start + (c << 5);
        if (c + 1 < nchunks && k + 32 + lane < end)
            scw[w][buf ^ 1][lane] = g_cw[k + 32 + lane];
        int cnt = end - k; if (cnt > 32) cnt = 32;
        int j = 0;
        for (; j + 8 <= cnt; j += 8) {
            int2 cc[8];
            #pragma unroll
            for (int u = 0; u < 8; u++) cc[u] = scw[w][buf][j + u];
            float2 v[8];
            #pragma unroll
            for (int u = 0; u < 8; u++) v[u] = __half22float2(h2[(cc[u].x << 5) + lane]);
            #pragma unroll
            for (int u = 0; u < 8; u++) {
                float wt = __int_as_float(cc[u].y);
                ax += wt * v[u].x; ay += wt * v[u].y;
            }
        }
        for (; j < cnt; j++) {
            int2 cc = scw[w][buf][j];
            float2 v = __half22float2(h2[(cc.x << 5) + lane]);
            float wt = __int_as_float(cc.y);
            ax += wt * v.x; ay += wt * v.y;
        }
        __syncwarp();
        buf ^= 1;
    }
    // head: relu(a3 + b3) @ Wl1 + bl1, relu, @ Wl2 + bl2
    sT[w][2 * lane]     = fmaxf(ax + sb3[2 * lane], 0.f);
    sT[w][2 * lane + 1] = fmaxf(ay + sb3[2 * lane + 1], 0.f);
    __syncwarp();
    float o = 0.f;
    if (lane < 20) {
        float m = sb1[lane];
        #pragma unroll 8
        for (int f = 0; f < 64; f++) m += sT[w][f] * sW1[f * 20 + lane];
        o = fmaxf(m, 0.f) * sW2[lane];
    }
    #pragma unroll
    for (int off = 16; off; off >>= 1) o += __shfl_down_sync(0xffffffffu, o, off);
    if (lane == 0) out[gw] = o + sb2;
}

// ---------------- launch ----------------
extern "C" void kernel_launch(void* const* d_in, const int* in_sizes, int n_in,
                              void* d_out, int out_size) {
    const float* x   = (const float*)d_in[0];
    const int*   ei  = (const int*)d_in[1];
    const float* W1  = (const float*)d_in[2];
    const float* b1  = (const float*)d_in[3];
    const float* W2  = (const float*)d_in[4];
    const float* b2  = (const float*)d_in[5];
    const float* W3  = (const float*)d_in[6];
    const float* b3  = (const float*)d_in[7];
    const float* Wl1 = (const float*)d_in[8];
    const float* bl1 = (const float*)d_in[9];
    const float* Wl2 = (const float*)d_in[10];
    const float* bl2 = (const float*)d_in[11];
    float* out = (float*)d_out;

    int n = in_sizes[0] / 21;
    int E = in_sizes[1] / 2;
    if (n > N_MAX) n = N_MAX;
    if (E > E_MAX) E = E_MAX;

    __half *x16, *abuf, *hbuf, *w1h, *w2h, *w3h;
    cudaGetSymbolAddress((void**)&x16, g_x16);
    cudaGetSymbolAddress((void**)&abuf, g_abuf);
    cudaGetSymbolAddress((void**)&hbuf, g_hbuf);
    cudaGetSymbolAddress((void**)&w1h, g_w1h);
    cudaGetSymbolAddress((void**)&w2h, g_w2h);
    cudaGetSymbolAddress((void**)&w3h, g_w3h);

    const int T = 256;
    int nb1024 = (n + 1023) / 1024;
    int aggBlocks = (n + 7) / 8;
    int gemmBlocks = (n + 63) / 64;

    k_pre<<<(n * 32 + T - 1) / T, T>>>(x, (const unsigned int*)ei, W1, W2, W3, n);
    k_deg<<<((E + 3) / 4 + T - 1) / T, T>>>(ei, E);
    k_scan<<<nb1024, 1024>>>(n, E);
    k_scatter<<<((E + 3) / 4 + T - 1) / T, T>>>(ei, E);

    // layer1: a1 = Â x16 (32), h1 = relu(a1 @ W1 + b1) -> hbuf[n,64]
    k_agg_h32<<<aggBlocks, T>>>(x16, abuf, n);
    k_hgemm<32, 64, 1, 1><<<gemmBlocks, 256>>>(abuf, w1h, b1, hbuf, n);

    // layer2: a2 = Â h1 (64), h2 = relu(a2 @ W2 + b2) -> hbuf[n,128]
    k_agg_h64<<<aggBlocks, T>>>((const __half2*)hbuf, (__half2*)abuf, n);
    k_hgemm<64, 128, 1, 1><<<gemmBlocks, 256>>>(abuf, w2h, b2, hbuf, n);

    // layer3: t = h2 @ W3 -> abuf[n,64]; fused a3 = Â t + head -> out
    k_hgemm<128, 64, 0, 0><<<gemmBlocks, 256>>>(hbuf, w3h, nullptr, abuf, n);
    k_agg_head<<<aggBlocks, T>>>((const __half2*)abuf, b3, Wl1, bl1, Wl2, bl2, out, n);
}

// round 9
// speedup vs baseline: 1.0311x; 1.0311x over previous
#include <cuda_runtime.h>
#include <cuda_fp16.h>
#include <mma.h>
#include <stdint.h>

using namespace nvcuda;

#define N_MAX 100000
#define E_MAX 3200000

// ---------------- scratch (static device globals; no allocation) ----------------
__device__ int   g_deg[N_MAX];
__device__ int   g_rowptr[N_MAX + 1];
__device__ int   g_cursor[N_MAX];
__device__ unsigned int g_blkpub[128];   // lookback word: bit31=inclusive, bit30=aggregate
__device__ int   g_cs[E_MAX];            // src index only (weights folded into features)
__device__ float g_dinv[N_MAX];
__device__ __align__(16) __half g_x16[N_MAX * 32];    // padded input fp16 (scaled by dinv in k_scan)
__device__ __align__(16) __half g_abuf[N_MAX * 64];   // agg outputs / t_scaled
__device__ __align__(16) __half g_hbuf[N_MAX * 128];  // h1_scaled, h2
__device__ __align__(16) __half g_w1h[32 * 64];       // W1 padded 21->32 rows
__device__ __align__(16) __half g_w2h[64 * 128];
__device__ __align__(16) __half g_w3h[128 * 64];
__device__ int   g_is64;

// ---------------- pre: sniff, pad x, zero deg + lookback flags, weights --------
__global__ void k_pre(const float* __restrict__ x, const unsigned int* __restrict__ ew,
                      const float* __restrict__ W1, const float* __restrict__ W2,
                      const float* __restrict__ W3, int n) {
    if (blockIdx.x == 0) {
        if (threadIdx.x == 0) g_is64 = 1;
        __syncthreads();
        bool hit = false;
        #pragma unroll 4
        for (int s = 0; s < 32; s++) {
            int i = threadIdx.x * 32 + s;
            if (ew[2 * i + 1] != 0u) hit = true;
        }
        if (hit) g_is64 = 0;
    }
    int idx = blockIdx.x * blockDim.x + threadIdx.x;
    if (idx < n * 32) {
        int i = idx >> 5, f = idx & 31;
        g_x16[idx] = __float2half((f < 21) ? x[i * 21 + f] : 0.f);
    }
    if (idx < n) g_deg[idx] = 0;
    if (idx < 128) g_blkpub[idx] = 0u;
    if (idx < 2048) {                 // W1 pad to 32x64
        int r = idx >> 6, c = idx & 63;
        g_w1h[idx] = __float2half((r < 21) ? W1[r * 64 + c] : 0.f);
    }
    if (idx < 8192) g_w2h[idx] = __float2half(W2[idx]);
    if (idx < 8192) g_w3h[idx] = __float2half(W3[idx]);
}

// ---------------- degree histogram: 4 edges per thread ----------------
__global__ void k_deg(const int* __restrict__ ei32, int E) {
    int e = (blockIdx.x * blockDim.x + threadIdx.x) << 2;
    if (e >= E) return;
    int is64 = g_is64;
    int m = E - e; if (m > 4) m = 4;
    if (((E & 3) == 0) && m == 4) {
        int d[4];
        if (is64) {
            const int4* p = (const int4*)((const long long*)ei32 + E + e);
            int4 q0 = p[0], q1 = p[1];
            d[0] = q0.x; d[1] = q0.z; d[2] = q1.x; d[3] = q1.z;
        } else {
            int4 q = *(const int4*)(ei32 + E + e);
            d[0] = q.x; d[1] = q.y; d[2] = q.z; d[3] = q.w;
        }
        atomicAdd(&g_deg[d[0]], 1); atomicAdd(&g_deg[d[1]], 1);
        atomicAdd(&g_deg[d[2]], 1); atomicAdd(&g_deg[d[3]], 1);
    } else {
        for (int j = 0; j < m; j++) {
            int dd = is64 ? ei32[(E + e + j) << 1] : ei32[E + e + j];
            atomicAdd(&g_deg[dd], 1);
        }
    }
}

// ---------------- single-pass scan (warp-parallel lookback) + dinv + scale x ---
__global__ void k_scan(int n, int E) {
    __shared__ int wsum[32];
    __shared__ int s_prefix;
    int tid = threadIdx.x, bid = blockIdx.x;
    int i = bid * 1024 + tid;
    int v = (i < n) ? g_deg[i] : 0;
    float dv = rsqrtf((float)(v + 1));   // self-loop included
    if (i < n) g_dinv[i] = dv;
    int lane = tid & 31, wid = tid >> 5;
    int inc = v;
    #pragma unroll
    for (int off = 1; off < 32; off <<= 1) {
        int t = __shfl_up_sync(0xffffffffu, inc, off);
        if (lane >= off) inc += t;
    }
    if (lane == 31) wsum[wid] = inc;
    __syncthreads();
    if (wid == 0) {
        int s = wsum[lane];
        #pragma unroll
        for (int off = 1; off < 32; off <<= 1) {
            int t = __shfl_up_sync(0xffffffffu, s, off);
            if (lane >= off) s += t;
        }
        wsum[lane] = s;
    }
    __syncthreads();
    int total = wsum[31];

    if (wid == 0) {
        if (bid == 0) {
            if (lane == 0) {
                atomicExch(&g_blkpub[0], 0x80000000u | (unsigned)total);
                s_prefix = 0;
                g_rowptr[n] = E;
            }
        } else {
            if (lane == 0)
                atomicExch(&g_blkpub[bid], 0x40000000u | (unsigned)total);
            // warp-parallel lookback: 32 predecessors per round
            int prefix = 0;
            int p = bid - 1;
            volatile unsigned* pub = g_blkpub;
            while (true) {
                int idx = p - lane;
                unsigned s = 0;
                if (idx >= 0) {
                    do { s = pub[idx]; } while (!(s & 0xC0000000u));
                }
                unsigned ball = __ballot_sync(0xffffffffu,
                                              idx >= 0 && (s & 0x80000000u));
                int L = ball ? (__ffs(ball) - 1) : 32;
                int contrib = (idx >= 0 && lane <= L) ? (int)(s & 0x3FFFFFFFu) : 0;
                #pragma unroll
                for (int off = 16; off; off >>= 1)
                    contrib += __shfl_xor_sync(0xffffffffu, contrib, off);
                prefix += contrib;
                if (ball) break;
                p -= 32;
            }
            if (lane == 0) {
                atomicExch(&g_blkpub[bid], 0x80000000u | (unsigned)(prefix + total));
                s_prefix = prefix;
            }
        }
    }
    __syncthreads();
    int base = (wid > 0) ? wsum[wid - 1] : 0;
    if (i < n) {
        int r = s_prefix + base + inc - v;   // exclusive
        g_rowptr[i] = r;
        g_cursor[i] = r;
        // scale x row by dinv (features become h_scaled for layer-1 agg)
        __half2* row = (__half2*)(g_x16 + ((size_t)i << 5));
        __half2 s2 = __floats2half2_rn(dv, dv);
        #pragma unroll
        for (int f = 0; f < 16; f++) row[f] = __hmul2(row[f], s2);
    }
}

// ---------------- CSR scatter: src only (4B per edge) ----------------
__global__ void k_scatter(const int* __restrict__ ei32, int E) {
    int e = (blockIdx.x * blockDim.x + threadIdx.x) << 2;
    if (e >= E) return;
    int is64 = g_is64;
    int m = E - e; if (m > 4) m = 4;
    if (((E & 3) == 0) && m == 4) {
        int s[4], d[4];
        if (is64) {
            const int4* ps = (const int4*)((const long long*)ei32 + e);
            int4 a0 = ps[0], a1 = ps[1];
            s[0] = a0.x; s[1] = a0.z; s[2] = a1.x; s[3] = a1.z;
            const int4* pd = (const int4*)((const long long*)ei32 + E + e);
            int4 b0 = pd[0], b1 = pd[1];
            d[0] = b0.x; d[1] = b0.z; d[2] = b1.x; d[3] = b1.z;
        } else {
            int4 a = *(const int4*)(ei32 + e);
            s[0] = a.x; s[1] = a.y; s[2] = a.z; s[3] = a.w;
            int4 b = *(const int4*)(ei32 + E + e);
            d[0] = b.x; d[1] = b.y; d[2] = b.z; d[3] = b.w;
        }
        #pragma unroll
        for (int j = 0; j < 4; j++) {
            int pos = atomicAdd(&g_cursor[d[j]], 1);
            g_cs[pos] = s[j];
        }
    } else {
        for (int j = 0; j < m; j++) {
            int src = is64 ? ei32[(e + j) << 1] : ei32[e + j];
            int dst = is64 ? ei32[(E + e + j) << 1] : ei32[E + e + j];
            int pos = atomicAdd(&g_cursor[dst], 1);
            g_cs[pos] = src;
        }
    }
}

// ---------------- aggregation: warp/node; gather pre-scaled rows, pure sum ------
// out[dst] = dinv[dst] * ( h_s[dst] + sum_src h_s[src] )
// 32 halfs per row
__global__ void k_agg_h32(const __half* __restrict__ h, __half* __restrict__ out, int n) {
    __shared__ int scs[8][2][32];
    int w = threadIdx.x >> 5, lane = threadIdx.x & 31;
    int gw = blockIdx.x * 8 + w;
    if (gw >= n) return;
    int start = g_rowptr[gw], end = g_rowptr[gw + 1];
    float acc = __half2float(h[(gw << 5) + lane]);      // self term
    int nchunks = (end - start + 31) >> 5;
    if (start + lane < end) scs[w][0][lane] = g_cs[start + lane];
    __syncwarp();
    int buf = 0;
    for (int c = 0; c < nchunks; c++) {
        int k = start + (c << 5);
        if (c + 1 < nchunks && k + 32 + lane < end)
            scs[w][buf ^ 1][lane] = g_cs[k + 32 + lane];
        int cnt = end - k; if (cnt > 32) cnt = 32;
        int j = 0;
        for (; j + 8 <= cnt; j += 8) {
            int cc[8];
            #pragma unroll
            for (int u = 0; u < 8; u++) cc[u] = scs[w][buf][j + u];
            float v[8];
            #pragma unroll
            for (int u = 0; u < 8; u++) v[u] = __half2float(h[(cc[u] << 5) + lane]);
            #pragma unroll
            for (int u = 0; u < 8; u++) acc += v[u];
        }
        for (; j < cnt; j++)
            acc += __half2float(h[(scs[w][buf][j] << 5) + lane]);
        __syncwarp();
        buf ^= 1;
    }
    out[(gw << 5) + lane] = __float2half_rn(g_dinv[gw] * acc);
}

// 64 halfs per row = 32 half2 per row
__global__ void k_agg_h64(const __half2* __restrict__ h2, __half2* __restrict__ o2, int n) {
    __shared__ int scs[8][2][32];
    int w = threadIdx.x >> 5, lane = threadIdx.x & 31;
    int gw = blockIdx.x * 8 + w;
    if (gw >= n) return;
    int start = g_rowptr[gw], end = g_rowptr[gw + 1];
    float2 hv = __half22float2(h2[(gw << 5) + lane]);
    float ax = hv.x, ay = hv.y;                          // self term
    int nchunks = (end - start + 31) >> 5;
    if (start + lane < end) scs[w][0][lane] = g_cs[start + lane];
    __syncwarp();
    int buf = 0;
    for (int c = 0; c < nchunks; c++) {
        int k = start + (c << 5);
        if (c + 1 < nchunks && k + 32 + lane < end)
            scs[w][buf ^ 1][lane] = g_cs[k + 32 + lane];
        int cnt = end - k; if (cnt > 32) cnt = 32;
        int j = 0;
        for (; j + 8 <= cnt; j += 8) {
            int cc[8];
            #pragma unroll
            for (int u = 0; u < 8; u++) cc[u] = scs[w][buf][j + u];
            float2 v[8];
            #pragma unroll
            for (int u = 0; u < 8; u++) v[u] = __half22float2(h2[(cc[u] << 5) + lane]);
            #pragma unroll
            for (int u = 0; u < 8; u++) { ax += v[u].x; ay += v[u].y; }
        }
        for (; j < cnt; j++) {
            float2 v = __half22float2(h2[(scs[w][buf][j] << 5) + lane]);
            ax += v.x; ay += v.y;
        }
        __syncwarp();
        buf ^= 1;
    }
    float dv = g_dinv[gw];
    o2[(gw << 5) + lane] = __floats2half2_rn(dv * ax, dv * ay);
}

// ---------------- HMMA GEMM: A[n,K]fp16 @ W[K,N]fp16 (+bias,relu,row-scale) -----
template<int K, int N, int RELU, int BIAS, int SCALE>
__global__ void k_hgemm(const __half* __restrict__ A, const __half* __restrict__ Wh,
                        const float* __restrict__ bias, __half* __restrict__ C, int n) {
    constexpr int CF = N / 64;
    constexpr int SZ_AB = (64 * K + K * N) * 2;
    constexpr int SZ_C = 64 * N * 4;
    constexpr int SZ = SZ_AB > SZ_C ? SZ_AB : SZ_C;
    __shared__ __align__(16) char smem[SZ];
    __half* sA = (__half*)smem;
    __half* sB = (__half*)(smem + 64 * K * 2);
    float*  sC = (float*)smem;

    int tid = threadIdx.x;
    int rowBase = blockIdx.x * 64;

    constexpr int AV = 64 * K / 8;
    for (int v = tid; v < AV; v += 256) {
        int r = v / (K / 8);
        int c8 = (v % (K / 8)) * 8;
        int4 val = make_int4(0, 0, 0, 0);
        int row = rowBase + r;
        if (row < n) val = *(const int4*)(A + (size_t)row * K + c8);
        *(int4*)(sA + r * K + c8) = val;
    }
    constexpr int BV = K * N / 8;
    for (int v = tid; v < BV; v += 256)
        *(int4*)(sB + v * 8) = *(const int4*)(Wh + v * 8);
    __syncthreads();

    int wid = tid >> 5;
    int wr = wid >> 2, wc = wid & 3;
    wmma::fragment<wmma::accumulator, 16, 16, 16, float> acc[2][CF];
    #pragma unroll
    for (int i = 0; i < 2; i++)
        #pragma unroll
        for (int j = 0; j < CF; j++)
            wmma::fill_fragment(acc[i][j], 0.f);

    #pragma unroll
    for (int k = 0; k < K; k += 16) {
        wmma::fragment<wmma::matrix_a, 16, 16, 16, __half, wmma::row_major> af[2];
        wmma::fragment<wmma::matrix_b, 16, 16, 16, __half, wmma::row_major> bf[CF];
        #pragma unroll
        for (int i = 0; i < 2; i++)
            wmma::load_matrix_sync(af[i], sA + (wr * 32 + i * 16) * K + k, K);
        #pragma unroll
        for (int j = 0; j < CF; j++)
            wmma::load_matrix_sync(bf[j], sB + k * N + (wc * CF + j) * 16, N);
        #pragma unroll
        for (int i = 0; i < 2; i++)
            #pragma unroll
            for (int j = 0; j < CF; j++)
                wmma::mma_sync(acc[i][j], af[i], bf[j], acc[i][j]);
    }
    __syncthreads();
    #pragma unroll
    for (int i = 0; i < 2; i++)
        #pragma unroll
        for (int j = 0; j < CF; j++)
            wmma::store_matrix_sync(sC + (wr * 32 + i * 16) * N + (wc * CF + j) * 16,
                                    acc[i][j], N, wmma::mem_row_major);
    __syncthreads();

    constexpr int EV = 64 * N / 4;
    for (int v = tid; v < EV; v += 256) {
        int r = v / (N / 4);
        int c4 = (v % (N / 4)) * 4;
        int row = rowBase + r;
        if (row >= n) continue;
        float4 p = *(const float4*)(sC + r * N + c4);
        float v0 = p.x, v1 = p.y, v2 = p.z, v3 = p.w;
        if (BIAS) {
            v0 += bias[c4]; v1 += bias[c4 + 1]; v2 += bias[c4 + 2]; v3 += bias[c4 + 3];
        }
        if (RELU) {
            v0 = fmaxf(v0, 0.f); v1 = fmaxf(v1, 0.f);
            v2 = fmaxf(v2, 0.f); v3 = fmaxf(v3, 0.f);
        }
        if (SCALE) {
            float dv = g_dinv[row];
            v0 *= dv; v1 *= dv; v2 *= dv; v3 *= dv;
        }
        __half2 h0 = __floats2half2_rn(v0, v1);
        __half2 h1 = __floats2half2_rn(v2, v3);
        *(int2*)(C + (size_t)row * N + c4) = make_int2(*(int*)&h0, *(int*)&h1);
    }
}

// ---------------- fused: a3 = dinv*(sum t_s) then head MLP ----------------------
__global__ void k_agg_head(const __half2* __restrict__ h2, const float* __restrict__ b3,
                           const float* __restrict__ Wl1, const float* __restrict__ bl1,
                           const float* __restrict__ Wl2, const float* __restrict__ bl2,
                           float* __restrict__ out, int n) {
    __shared__ int scs[8][2][32];
    __shared__ float sW1[64 * 20];
    __shared__ float sT[8][64];
    __shared__ float sb3[64], sb1[20], sW2[20];
    __shared__ float sb2;
    int tid = threadIdx.x;
    for (int i = tid; i < 1280; i += 256) sW1[i] = Wl1[i];
    if (tid < 64) sb3[tid] = b3[tid];
    if (tid < 20) { sb1[tid] = bl1[tid]; sW2[tid] = Wl2[tid]; }
    if (tid == 0) sb2 = bl2[0];
    __syncthreads();

    int w = tid >> 5, lane = tid & 31;
    int gw = blockIdx.x * 8 + w;
    if (gw >= n) return;
    int start = g_rowptr[gw], end = g_rowptr[gw + 1];
    float2 hv = __half22float2(h2[(gw << 5) + lane]);
    float ax = hv.x, ay = hv.y;
    int nchunks = (end - start + 31) >> 5;
    if (start + lane < end) scs[w][0][lane] = g_cs[start + lane];
    __syncwarp();
    int buf = 0;
    for (int c = 0; c < nchunks; c++) {
        int k = start + (c << 5);
        if (c + 1 < nchunks && k + 32 + lane < end)
            scs[w][buf ^ 1][lane] = g_cs[k + 32 + lane];
        int cnt = end - k; if (cnt > 32) cnt = 32;
        int j = 0;
        for (; j + 8 <= cnt; j += 8) {
            int cc[8];
            #pragma unroll
            for (int u = 0; u < 8; u++) cc[u] = scs[w][buf][j + u];
            float2 v[8];
            #pragma unroll
            for (int u = 0; u < 8; u++) v[u] = __half22float2(h2[(cc[u] << 5) + lane]);
            #pragma unroll
            for (int u = 0; u < 8; u++) { ax += v[u].x; ay += v[u].y; }
        }
        for (; j < cnt; j++) {
            float2 v = __half22float2(h2[(scs[w][buf][j] << 5) + lane]);
            ax += v.x; ay += v.y;
        }
        __syncwarp();
        buf ^= 1;
    }
    float dv = g_dinv[gw];
    // head: relu(a3 + b3) @ Wl1 + bl1, relu, @ Wl2 + bl2
    sT[w][2 * lane]     = fmaxf(dv * ax + sb3[2 * lane], 0.f);
    sT[w][2 * lane + 1] = fmaxf(dv * ay + sb3[2 * lane + 1], 0.f);
    __syncwarp();
    float o = 0.f;
    if (lane < 20) {
        float m = sb1[lane];
        #pragma unroll 8
        for (int f = 0; f < 64; f++) m += sT[w][f] * sW1[f * 20 + lane];
        o = fmaxf(m, 0.f) * sW2[lane];
    }
    #pragma unroll
    for (int off = 16; off; off >>= 1) o += __shfl_down_sync(0xffffffffu, o, off);
    if (lane == 0) out[gw] = o + sb2;
}

// ---------------- launch ----------------
extern "C" void kernel_launch(void* const* d_in, const int* in_sizes, int n_in,
                              void* d_out, int out_size) {
    const float* x   = (const float*)d_in[0];
    const int*   ei  = (const int*)d_in[1];
    const float* W1  = (const float*)d_in[2];
    const float* b1  = (const float*)d_in[3];
    const float* W2  = (const float*)d_in[4];
    const float* b2  = (const float*)d_in[5];
    const float* W3  = (const float*)d_in[6];
    const float* b3  = (const float*)d_in[7];
    const float* Wl1 = (const float*)d_in[8];
    const float* bl1 = (const float*)d_in[9];
    const float* Wl2 = (const float*)d_in[10];
    const float* bl2 = (const float*)d_in[11];
    float* out = (float*)d_out;

    int n = in_sizes[0] / 21;
    int E = in_sizes[1] / 2;
    if (n > N_MAX) n = N_MAX;
    if (E > E_MAX) E = E_MAX;

    __half *x16, *abuf, *hbuf, *w1h, *w2h, *w3h;
    cudaGetSymbolAddress((void**)&x16, g_x16);
    cudaGetSymbolAddress((void**)&abuf, g_abuf);
    cudaGetSymbolAddress((void**)&hbuf, g_hbuf);
    cudaGetSymbolAddress((void**)&w1h, g_w1h);
    cudaGetSymbolAddress((void**)&w2h, g_w2h);
    cudaGetSymbolAddress((void**)&w3h, g_w3h);

    const int T = 256;
    int nb1024 = (n + 1023) / 1024;
    int aggBlocks = (n + 7) / 8;
    int gemmBlocks = (n + 63) / 64;

    k_pre<<<(n * 32 + T - 1) / T, T>>>(x, (const unsigned int*)ei, W1, W2, W3, n);
    k_deg<<<((E + 3) / 4 + T - 1) / T, T>>>(ei, E);
    k_scan<<<nb1024, 1024>>>(n, E);
    k_scatter<<<((E + 3) / 4 + T - 1) / T, T>>>(ei, E);

    // layer1: a1 = Â x (via scaled x16), h1_s = dinv*relu(a1@W1+b1) -> hbuf[n,64]
    k_agg_h32<<<aggBlocks, T>>>(x16, abuf, n);
    k_hgemm<32, 64, 1, 1, 1><<<gemmBlocks, 256>>>(abuf, w1h, b1, hbuf, n);

    // layer2: a2 = Â h1, h2 = relu(a2@W2+b2) (unscaled) -> hbuf[n,128]
    k_agg_h64<<<aggBlocks, T>>>((const __half2*)hbuf, (__half2*)abuf, n);
    k_hgemm<64, 128, 1, 1, 0><<<gemmBlocks, 256>>>(abuf, w2h, b2, hbuf, n);

    // layer3: t_s = dinv*(h2@W3) -> abuf[n,64]; fused a3 = Â t + head -> out
    k_hgemm<128, 64, 0, 0, 1><<<gemmBlocks, 256>>>(hbuf, w3h, nullptr, abuf, n);
    k_agg_head<<<aggBlocks, T>>>((const __half2*)abuf, b3, Wl1, bl1, Wl2, bl2, out, n);
}

// round 15
// speedup vs baseline: 1.0497x; 1.0181x over previous
#include <cuda_runtime.h>
#include <cuda_fp16.h>
#include <mma.h>
#include <stdint.h>

using namespace nvcuda;

#define N_MAX 100000
#define E_MAX 3200000

// ---------------- scratch (static device globals; no allocation) ----------------
__device__ int   g_deg[N_MAX];
__device__ int   g_rowptr[N_MAX + 1];
__device__ int   g_cursor[N_MAX];
__device__ unsigned int g_blkpub[128];   // lookback word: bit31=inclusive, bit30=aggregate
__device__ int   g_cs[E_MAX];            // src index only (weights folded into features)
__device__ float g_dinv[N_MAX];
__device__ __align__(16) __half g_x16[N_MAX * 32];    // padded input fp16 (scaled by dinv in k_scan)
__device__ __align__(16) __half g_abuf[N_MAX * 64];   // agg outputs / t_scaled
__device__ __align__(16) __half g_hbuf[N_MAX * 128];  // h1_scaled, h2
__device__ __align__(16) __half g_w1h[32 * 64];       // W1 padded 21->32 rows
__device__ __align__(16) __half g_w2h[64 * 128];
__device__ __align__(16) __half g_w3h[128 * 64];
__device__ int   g_is64;

// ---------------- fused pre + degree histogram (block-local dtype sniff) --------
// g_deg and g_blkpub are zeroed by cudaMemsetAsync before this kernel.
__global__ void k_pre_deg(const float* __restrict__ x, const int* __restrict__ ei32,
                          const float* __restrict__ W1, const float* __restrict__ W2,
                          const float* __restrict__ W3, int n, int E) {
    __shared__ int s_is64;
    int tid = threadIdx.x, bid = blockIdx.x;
    int idx = bid * 256 + tid;

    // ---- pre work: pad x to 32 fp16 cols, convert weights ----
    if (idx < n * 32) {
        int i = idx >> 5, f = idx & 31;
        g_x16[idx] = __float2half((f < 21) ? x[i * 21 + f] : 0.f);
    }
    if (idx < 2048) {                 // W1 pad to 32x64
        int r = idx >> 6, c = idx & 63;
        g_w1h[idx] = __float2half((r < 21) ? W1[r * 64 + c] : 0.f);
    }
    if (idx < 8192) g_w2h[idx] = __float2half(W2[idx]);
    if (idx < 8192) g_w3h[idx] = __float2half(W3[idx]);

    // ---- edge work: 2048 dst-edges per block, block-local sniff ----
    int ebase = bid * 2048;
    if (ebase < E) {
        if (tid == 0) s_is64 = 1;
        __syncthreads();
        // sniff this block's own slice: int64 -> odd 32-bit words are zero hi-halves;
        // int32 -> odd words are node ids (all-zero over >=1024 words: P ~ (1e-5)^1024)
        const unsigned int* ew = (const unsigned int*)ei32;
        bool hit = false;
        #pragma unroll
        for (int s = 0; s < 8; s++) {
            int e = ebase + tid + s * 256;
            if (e < E && ew[2 * e + 1] != 0u) hit = true;
        }
        if (hit) s_is64 = 0;
        __syncthreads();
        int is64 = s_is64;
        if (bid == 0 && tid == 0) g_is64 = is64;   // publish for k_scatter
        #pragma unroll
        for (int s = 0; s < 8; s++) {
            int e = ebase + tid + s * 256;
            if (e < E) {
                int dd = is64 ? ei32[2 * (E + e)] : ei32[E + e];
                atomicAdd(&g_deg[dd], 1);
            }
        }
    }
}

// ---------------- single-pass scan (warp-parallel lookback) + dinv + scale x ---
__global__ void k_scan(int n, int E) {
    __shared__ int wsum[32];
    __shared__ int s_prefix;
    int tid = threadIdx.x, bid = blockIdx.x;
    int i = bid * 1024 + tid;
    int v = (i < n) ? g_deg[i] : 0;
    float dv = rsqrtf((float)(v + 1));   // self-loop included
    if (i < n) g_dinv[i] = dv;
    int lane = tid & 31, wid = tid >> 5;
    int inc = v;
    #pragma unroll
    for (int off = 1; off < 32; off <<= 1) {
        int t = __shfl_up_sync(0xffffffffu, inc, off);
        if (lane >= off) inc += t;
    }
    if (lane == 31) wsum[wid] = inc;
    __syncthreads();
    if (wid == 0) {
        int s = wsum[lane];
        #pragma unroll
        for (int off = 1; off < 32; off <<= 1) {
            int t = __shfl_up_sync(0xffffffffu, s, off);
            if (lane >= off) s += t;
        }
        wsum[lane] = s;
    }
    __syncthreads();
    int total = wsum[31];

    if (wid == 0) {
        if (bid == 0) {
            if (lane == 0) {
                atomicExch(&g_blkpub[0], 0x80000000u | (unsigned)total);
                s_prefix = 0;
                g_rowptr[n] = E;
            }
        } else {
            if (lane == 0)
                atomicExch(&g_blkpub[bid], 0x40000000u | (unsigned)total);
            // warp-parallel lookback: 32 predecessors per round
            int prefix = 0;
            int p = bid - 1;
            volatile unsigned* pub = g_blkpub;
            while (true) {
                int idx = p - lane;
                unsigned s = 0;
                if (idx >= 0) {
                    do { s = pub[idx]; } while (!(s & 0xC0000000u));
                }
                unsigned ball = __ballot_sync(0xffffffffu,
                                              idx >= 0 && (s & 0x80000000u));
                int L = ball ? (__ffs(ball) - 1) : 32;
                int contrib = (idx >= 0 && lane <= L) ? (int)(s & 0x3FFFFFFFu) : 0;
                #pragma unroll
                for (int off = 16; off; off >>= 1)
                    contrib += __shfl_xor_sync(0xffffffffu, contrib, off);
                prefix += contrib;
                if (ball) break;
                p -= 32;
            }
            if (lane == 0) {
                atomicExch(&g_blkpub[bid], 0x80000000u | (unsigned)(prefix + total));
                s_prefix = prefix;
            }
        }
    }
    __syncthreads();
    int base = (wid > 0) ? wsum[wid - 1] : 0;
    if (i < n) {
        int r = s_prefix + base + inc - v;   // exclusive
        g_rowptr[i] = r;
        g_cursor[i] = r;
        // scale x row by dinv (features become h_scaled for layer-1 agg)
        __half2* row = (__half2*)(g_x16 + ((size_t)i << 5));
        __half2 s2 = __floats2half2_rn(dv, dv);
        #pragma unroll
        for (int f = 0; f < 16; f++) row[f] = __hmul2(row[f], s2);
    }
}

// ---------------- CSR scatter: 8 edges/thread (MLP=8 on atomic chains) ----------
__global__ void k_scatter(const int* __restrict__ ei32, int E) {
    int base = (blockIdx.x * blockDim.x + threadIdx.x) << 3;
    if (base >= E) return;
    int is64 = g_is64;
    int m = E - base; if (m > 8) m = 8;
    int s[8], d[8];
    #pragma unroll
    for (int j = 0; j < 8; j++) {
        if (j < m) {
            s[j] = is64 ? ei32[2 * (base + j)] : ei32[base + j];
            d[j] = is64 ? ei32[2 * (E + base + j)] : ei32[E + base + j];
        }
    }
    int pos[8];
    #pragma unroll
    for (int j = 0; j < 8; j++)
        if (j < m) pos[j] = atomicAdd(&g_cursor[d[j]], 1);
    #pragma unroll
    for (int j = 0; j < 8; j++)
        if (j < m) g_cs[pos[j]] = s[j];
}

// ---------------- aggregation: warp/node; 64-edge chunks, double-buffered -------
// out[dst] = dinv[dst] * ( h_s[dst] + sum_src h_s[src] )
// 32 halfs per row
__global__ void k_agg_h32(const __half* __restrict__ h, __half* __restrict__ out, int n) {
    __shared__ int scs[8][2][64];
    int w = threadIdx.x >> 5, lane = threadIdx.x & 31;
    int gw = blockIdx.x * 8 + w;
    if (gw >= n) return;
    int start = g_rowptr[gw], end = g_rowptr[gw + 1];
    float acc = __half2float(h[(gw << 5) + lane]);      // self term
    int nchunks = (end - start + 63) >> 6;
    if (start + lane < end) scs[w][0][lane] = g_cs[start + lane];
    if (start + 32 + lane < end) scs[w][0][32 + lane] = g_cs[start + 32 + lane];
    __syncwarp();
    int buf = 0;
    for (int c = 0; c < nchunks; c++) {
        int k = start + (c << 6);
        int nk = k + 64;
        if (c + 1 < nchunks) {
            if (nk + lane < end) scs[w][buf ^ 1][lane] = g_cs[nk + lane];
            if (nk + 32 + lane < end) scs[w][buf ^ 1][32 + lane] = g_cs[nk + 32 + lane];
        }
        int cnt = end - k; if (cnt > 64) cnt = 64;
        int j = 0;
        for (; j + 8 <= cnt; j += 8) {
            int cc[8];
            #pragma unroll
            for (int u = 0; u < 8; u++) cc[u] = scs[w][buf][j + u];
            float v[8];
            #pragma unroll
            for (int u = 0; u < 8; u++) v[u] = __half2float(h[(cc[u] << 5) + lane]);
            #pragma unroll
            for (int u = 0; u < 8; u++) acc += v[u];
        }
        for (; j < cnt; j++)
            acc += __half2float(h[(scs[w][buf][j] << 5) + lane]);
        __syncwarp();
        buf ^= 1;
    }
    out[(gw << 5) + lane] = __float2half_rn(g_dinv[gw] * acc);
}

// 64 halfs per row = 32 half2 per row
__global__ void k_agg_h64(const __half2* __restrict__ h2, __half2* __restrict__ o2, int n) {
    __shared__ int scs[8][2][64];
    int w = threadIdx.x >> 5, lane = threadIdx.x & 31;
    int gw = blockIdx.x * 8 + w;
    if (gw >= n) return;
    int start = g_rowptr[gw], end = g_rowptr[gw + 1];
    float2 hv = __half22float2(h2[(gw << 5) + lane]);
    float ax = hv.x, ay = hv.y;                          // self term
    int nchunks = (end - start + 63) >> 6;
    if (start + lane < end) scs[w][0][lane] = g_cs[start + lane];
    if (start + 32 + lane < end) scs[w][0][32 + lane] = g_cs[start + 32 + lane];
    __syncwarp();
    int buf = 0;
    for (int c = 0; c < nchunks; c++) {
        int k = start + (c << 6);
        int nk = k + 64;
        if (c + 1 < nchunks) {
            if (nk + lane < end) scs[w][buf ^ 1][lane] = g_cs[nk + lane];
            if (nk + 32 + lane < end) scs[w][buf ^ 1][32 + lane] = g_cs[nk + 32 + lane];
        }
        int cnt = end - k; if (cnt > 64) cnt = 64;
        int j = 0;
        for (; j + 8 <= cnt; j += 8) {
            int cc[8];
            #pragma unroll
            for (int u = 0; u < 8; u++) cc[u] = scs[w][buf][j + u];
            float2 v[8];
            #pragma unroll
            for (int u = 0; u < 8; u++) v[u] = __half22float2(h2[(cc[u] << 5) + lane]);
            #pragma unroll
            for (int u = 0; u < 8; u++) { ax += v[u].x; ay += v[u].y; }
        }
        for (; j < cnt; j++) {
            float2 v = __half22float2(h2[(scs[w][buf][j] << 5) + lane]);
            ax += v.x; ay += v.y;
        }
        __syncwarp();
        buf ^= 1;
    }
    float dv = g_dinv[gw];
    o2[(gw << 5) + lane] = __floats2half2_rn(dv * ax, dv * ay);
}

// ---------------- HMMA GEMM: A[n,K]fp16 @ W[K,N]fp16 (+bias,relu,row-scale) -----
template<int K, int N, int RELU, int BIAS, int SCALE>
__global__ void k_hgemm(const __half* __restrict__ A, const __half* __restrict__ Wh,
                        const float* __restrict__ bias, __half* __restrict__ C, int n) {
    constexpr int CF = N / 64;
    constexpr int SZ_AB = (64 * K + K * N) * 2;
    constexpr int SZ_C = 64 * N * 4;
    constexpr int SZ = SZ_AB > SZ_C ? SZ_AB : SZ_C;
    __shared__ __align__(16) char smem[SZ];
    __half* sA = (__half*)smem;
    __half* sB = (__half*)(smem + 64 * K * 2);
    float*  sC = (float*)smem;

    int tid = threadIdx.x;
    int rowBase = blockIdx.x * 64;

    constexpr int AV = 64 * K / 8;
    for (int v = tid; v < AV; v += 256) {
        int r = v / (K / 8);
        int c8 = (v % (K / 8)) * 8;
        int4 val = make_int4(0, 0, 0, 0);
        int row = rowBase + r;
        if (row < n) val = *(const int4*)(A + (size_t)row * K + c8);
        *(int4*)(sA + r * K + c8) = val;
    }
    constexpr int BV = K * N / 8;
    for (int v = tid; v < BV; v += 256)
        *(int4*)(sB + v * 8) = *(const int4*)(Wh + v * 8);
    __syncthreads();

    int wid = tid >> 5;
    int wr = wid >> 2, wc = wid & 3;
    wmma::fragment<wmma::accumulator, 16, 16, 16, float> acc[2][CF];
    #pragma unroll
    for (int i = 0; i < 2; i++)
        #pragma unroll
        for (int j = 0; j < CF; j++)
            wmma::fill_fragment(acc[i][j], 0.f);

    #pragma unroll
    for (int k = 0; k < K; k += 16) {
        wmma::fragment<wmma::matrix_a, 16, 16, 16, __half, wmma::row_major> af[2];
        wmma::fragment<wmma::matrix_b, 16, 16, 16, __half, wmma::row_major> bf[CF];
        #pragma unroll
        for (int i = 0; i < 2; i++)
            wmma::load_matrix_sync(af[i], sA + (wr * 32 + i * 16) * K + k, K);
        #pragma unroll
        for (int j = 0; j < CF; j++)
            wmma::load_matrix_sync(bf[j], sB + k * N + (wc * CF + j) * 16, N);
        #pragma unroll
        for (int i = 0; i < 2; i++)
            #pragma unroll
            for (int j = 0; j < CF; j++)
                wmma::mma_sync(acc[i][j], af[i], bf[j], acc[i][j]);
    }
    __syncthreads();
    #pragma unroll
    for (int i = 0; i < 2; i++)
        #pragma unroll
        for (int j = 0; j < CF; j++)
            wmma::store_matrix_sync(sC + (wr * 32 + i * 16) * N + (wc * CF + j) * 16,
                                    acc[i][j], N, wmma::mem_row_major);
    __syncthreads();

    constexpr int EV = 64 * N / 4;
    for (int v = tid; v < EV; v += 256) {
        int r = v / (N / 4);
        int c4 = (v % (N / 4)) * 4;
        int row = rowBase + r;
        if (row >= n) continue;
        float4 p = *(const float4*)(sC + r * N + c4);
        float v0 = p.x, v1 = p.y, v2 = p.z, v3 = p.w;
        if (BIAS) {
            v0 += bias[c4]; v1 += bias[c4 + 1]; v2 += bias[c4 + 2]; v3 += bias[c4 + 3];
        }
        if (RELU) {
            v0 = fmaxf(v0, 0.f); v1 = fmaxf(v1, 0.f);
            v2 = fmaxf(v2, 0.f); v3 = fmaxf(v3, 0.f);
        }
        if (SCALE) {
            float dv = g_dinv[row];
            v0 *= dv; v1 *= dv; v2 *= dv; v3 *= dv;
        }
        __half2 h0 = __floats2half2_rn(v0, v1);
        __half2 h1 = __floats2half2_rn(v2, v3);
        *(int2*)(C + (size_t)row * N + c4) = make_int2(*(int*)&h0, *(int*)&h1);
    }
}

// ---------------- fused: a3 = dinv*(sum t_s) then head MLP ----------------------
__global__ void k_agg_head(const __half2* __restrict__ h2, const float* __restrict__ b3,
                           const float* __restrict__ Wl1, const float* __restrict__ bl1,
                           const float* __restrict__ Wl2, const float* __restrict__ bl2,
                           float* __restrict__ out, int n) {
    __shared__ int scs[8][2][64];
    __shared__ float sW1[64 * 20];
    __shared__ float sT[8][64];
    __shared__ float sb3[64], sb1[20], sW2[20];
    __shared__ float sb2;
    int tid = threadIdx.x;
    for (int i = tid; i < 1280; i += 256) sW1[i] = Wl1[i];
    if (tid < 64) sb3[tid] = b3[tid];
    if (tid < 20) { sb1[tid] = bl1[tid]; sW2[tid] = Wl2[tid]; }
    if (tid == 0) sb2 = bl2[0];
    __syncthreads();

    int w = tid >> 5, lane = tid & 31;
    int gw = blockIdx.x * 8 + w;
    if (gw >= n) return;
    int start = g_rowptr[gw], end = g_rowptr[gw + 1];
    float2 hv = __half22float2(h2[(gw << 5) + lane]);
    float ax = hv.x, ay = hv.y;
    int nchunks = (end - start + 63) >> 6;
    if (start + lane < end) scs[w][0][lane] = g_cs[start + lane];
    if (start + 32 + lane < end) scs[w][0][32 + lane] = g_cs[start + 32 + lane];
    __syncwarp();
    int buf = 0;
    for (int c = 0; c < nchunks; c++) {
        int k = start + (c << 6);
        int nk = k + 64;
        if (c + 1 < nchunks) {
            if (nk + lane < end) scs[w][buf ^ 1][lane] = g_cs[nk + lane];
            if (nk + 32 + lane < end) scs[w][buf ^ 1][32 + lane] = g_cs[nk + 32 + lane];
        }
        int cnt = end - k; if (cnt > 64) cnt = 64;
        int j = 0;
        for (; j + 8 <= cnt; j += 8) {
            int cc[8];
            #pragma unroll
            for (int u = 0; u < 8; u++) cc[u] = scs[w][buf][j + u];
            float2 v[8];
            #pragma unroll
            for (int u = 0; u < 8; u++) v[u] = __half22float2(h2[(cc[u] << 5) + lane]);
            #pragma unroll
            for (int u = 0; u < 8; u++) { ax += v[u].x; ay += v[u].y; }
        }
        for (; j < cnt; j++) {
            float2 v = __half22float2(h2[(scs[w][buf][j] << 5) + lane]);
            ax += v.x; ay += v.y;
        }
        __syncwarp();
        buf ^= 1;
    }
    float dv = g_dinv[gw];
    // head: relu(a3 + b3) @ Wl1 + bl1, relu, @ Wl2 + bl2
    sT[w][2 * lane]     = fmaxf(dv * ax + sb3[2 * lane], 0.f);
    sT[w][2 * lane + 1] = fmaxf(dv * ay + sb3[2 * lane + 1], 0.f);
    __syncwarp();
    float o = 0.f;
    if (lane < 20) {
        float m = sb1[lane];
        #pragma unroll 8
        for (int f = 0; f < 64; f++) m += sT[w][f] * sW1[f * 20 + lane];
        o = fmaxf(m, 0.f) * sW2[lane];
    }
    #pragma unroll
    for (int off = 16; off; off >>= 1) o += __shfl_down_sync(0xffffffffu, o, off);
    if (lane == 0) out[gw] = o + sb2;
}

// ---------------- launch ----------------
extern "C" void kernel_launch(void* const* d_in, const int* in_sizes, int n_in,
                              void* d_out, int out_size) {
    const float* x   = (const float*)d_in[0];
    const int*   ei  = (const int*)d_in[1];
    const float* W1  = (const float*)d_in[2];
    const float* b1  = (const float*)d_in[3];
    const float* W2  = (const float*)d_in[4];
    const float* b2  = (const float*)d_in[5];
    const float* W3  = (const float*)d_in[6];
    const float* b3  = (const float*)d_in[7];
    const float* Wl1 = (const float*)d_in[8];
    const float* bl1 = (const float*)d_in[9];
    const float* Wl2 = (const float*)d_in[10];
    const float* bl2 = (const float*)d_in[11];
    float* out = (float*)d_out;

    int n = in_sizes[0] / 21;
    int E = in_sizes[1] / 2;
    if (n > N_MAX) n = N_MAX;
    if (E > E_MAX) E = E_MAX;

    __half *x16, *abuf, *hbuf, *w1h, *w2h, *w3h;
    cudaGetSymbolAddress((void**)&x16, g_x16);
    cudaGetSymbolAddress((void**)&abuf, g_abuf);
    cudaGetSymbolAddress((void**)&hbuf, g_hbuf);
    cudaGetSymbolAddress((void**)&w1h, g_w1h);
    cudaGetSymbolAddress((void**)&w2h, g_w2h);
    cudaGetSymbolAddress((void**)&w3h, g_w3h);

    void *degp, *blkp;
    cudaGetSymbolAddress(&degp, g_deg);
    cudaGetSymbolAddress(&blkp, g_blkpub);

    const int T = 256;
    int nb1024 = (n + 1023) / 1024;
    int aggBlocks = (n + 7) / 8;
    int gemmBlocks = (n + 63) / 64;
    int preBlocks = (n * 32 + T - 1) / T;
    int edgeBlocksNeeded = (E + 2047) / 2048;
    if (preBlocks < edgeBlocksNeeded) preBlocks = edgeBlocksNeeded;

    cudaMemsetAsync(degp, 0, (size_t)n * sizeof(int));
    cudaMemsetAsync(blkp, 0, 128 * sizeof(unsigned int));

    k_pre_deg<<<preBlocks, T>>>(x, ei, W1, W2, W3, n, E);
    k_scan<<<nb1024, 1024>>>(n, E);
    k_scatter<<<((E + 7) / 8 + T - 1) / T, T>>>(ei, E);

    // layer1: a1 = Â x (via scaled x16), h1_s = dinv*relu(a1@W1+b1) -> hbuf[n,64]
    k_agg_h32<<<aggBlocks, T>>>(x16, abuf, n);
    k_hgemm<32, 64, 1, 1, 1><<<gemmBlocks, 256>>>(abuf, w1h, b1, hbuf, n);

    // layer2: a2 = Â h1, h2 = relu(a2@W2+b2) (unscaled) -> hbuf[n,128]
    k_agg_h64<<<aggBlocks, T>>>((const __half2*)hbuf, (__half2*)abuf, n);
    k_hgemm<64, 128, 1, 1, 0><<<gemmBlocks, 256>>>(abuf, w2h, b2, hbuf, n);

    // layer3: t_s = dinv*(h2@W3) -> abuf[n,64]; fused a3 = Â t + head -> out
    k_hgemm<128, 64, 0, 0, 1><<<gemmBlocks, 256>>>(hbuf, w3h, nullptr, abuf, n);
    k_agg_head<<<aggBlocks, T>>>((const __half2*)abuf, b3, Wl1, bl1, Wl2, bl2, out, n);
}